// round 8
// baseline (speedup 1.0000x reference)
#include <cuda_runtime.h>
#include <cuda_fp16.h>
#include <cstdint>

#define T_TOK   8192
#define H_DIM   1024
#define I_DIM   512
#define E_EXP   8
#define EZ_EXP  12
#define SCALE_F 2.5f

typedef unsigned int u32;
typedef unsigned long long u64;

// ---------------- scratch (device globals; no allocation) ----------------
__device__ int    g_top_idx[T_TOK * 2];
__device__ float  g_top_w[T_TOK * 2];
__device__ float  g_zero_scale[T_TOK];
__device__ int    g_counts[E_EXP];
__device__ int    g_blk[E_EXP][16];
__device__ int    g_rows[E_EXP * T_TOK];
__device__ __half g_xh[(size_t)T_TOK * H_DIM];
__device__ __half g_w13h[(size_t)E_EXP * 2 * I_DIM * H_DIM];
__device__ __half g_w2h[(size_t)E_EXP * H_DIM * I_DIM];
__device__ __half g_acth[(size_t)T_TOK * 2 * I_DIM];
__device__ __half g_yh[(size_t)T_TOK * 2 * H_DIM];

// ---------------- helpers ----------------
__device__ __forceinline__ u32 smem_u32(const void* p) {
    u32 a;
    asm("{ .reg .u64 t; cvta.to.shared.u64 t, %1; cvt.u32.u64 %0, t; }" : "=r"(a) : "l"(p));
    return a;
}

#define CPA16(dst, src) \
    asm volatile("{.reg .u64 g; cvta.to.global.u64 g, %1; cp.async.cg.shared.global [%0], [g], 16;}\n" \
                 :: "r"((u32)(dst)), "l"(src) : "memory")
#define CPCOMMIT() asm volatile("cp.async.commit_group;" ::: "memory")
#define CPWAIT2()  asm volatile("cp.async.wait_group 2;" ::: "memory")
#define CPWAIT0()  asm volatile("cp.async.wait_group 0;" ::: "memory")

__device__ __forceinline__ void ldsm4(u32& r0, u32& r1, u32& r2, u32& r3, u32 addr) {
    asm volatile("ldmatrix.sync.aligned.m8n8.x4.shared.b16 {%0,%1,%2,%3}, [%4];"
                 : "=r"(r0), "=r"(r1), "=r"(r2), "=r"(r3) : "r"(addr));
}

__device__ __forceinline__ void mma_f16(float* d, const u32* a, u32 b0, u32 b1) {
    asm volatile("mma.sync.aligned.m16n8k16.row.col.f32.f16.f16.f32 "
        "{%0,%1,%2,%3}, {%4,%5,%6,%7}, {%8,%9}, {%0,%1,%2,%3};"
        : "+f"(d[0]), "+f"(d[1]), "+f"(d[2]), "+f"(d[3])
        : "r"(a[0]), "r"(a[1]), "r"(a[2]), "r"(a[3]), "r"(b0), "r"(b1));
}

// ============================================================================
// weight conversion (one-time)
// ============================================================================
#define W13_ELEMS ((size_t)E_EXP * 2 * I_DIM * H_DIM)
__global__ void __launch_bounds__(256) cvt_w_kernel(
    const float* __restrict__ w13, const float* __restrict__ w2)
{
    const size_t gid = (size_t)blockIdx.x * 256 + threadIdx.x;
    const float* src; __half* dst; size_t off;
    if (gid < W13_ELEMS / 4) { src = w13; dst = g_w13h; off = gid * 4; }
    else { src = w2; dst = g_w2h; off = (gid - W13_ELEMS / 4) * 4; }
    const float4 v = *(const float4*)(src + off);
    *(__half2*)(dst + off)     = __halves2half2(__float2half_rn(v.x), __float2half_rn(v.y));
    *(__half2*)(dst + off + 2) = __halves2half2(__float2half_rn(v.z), __float2half_rn(v.w));
}

// ============================================================================
// router + fused x -> fp16 conversion (proven)
// ============================================================================
__global__ void __launch_bounds__(256) router_kernel(
    const float* __restrict__ x, const float* __restrict__ rw, const float* __restrict__ bias)
{
    __shared__ float srw[EZ_EXP * H_DIM];
    const int tid = threadIdx.x;
    for (int i = tid; i < EZ_EXP * H_DIM; i += 256) srw[i] = rw[i];
    __syncthreads();

    const int warp = tid >> 5, lane = tid & 31;
    const int t = blockIdx.x * 8 + warp;
    const float* xr = x + (size_t)t * H_DIM;

    float xv[32];
#pragma unroll
    for (int j = 0; j < 32; j++) xv[j] = xr[lane + 32 * j];

    __half* xhw = g_xh + (size_t)t * H_DIM;
#pragma unroll
    for (int j = 0; j < 32; j++) xhw[lane + 32 * j] = __float2half_rn(xv[j]);

    float logits[EZ_EXP];
#pragma unroll
    for (int e = 0; e < EZ_EXP; e++) {
        const float* wr = srw + e * H_DIM;
        float acc = 0.f;
#pragma unroll
        for (int j = 0; j < 32; j++) acc += xv[j] * wr[lane + 32 * j];
#pragma unroll
        for (int off = 16; off; off >>= 1) acc += __shfl_xor_sync(0xffffffffu, acc, off);
        logits[e] = acc;
    }

    if (lane == 0) {
        float mx = logits[0];
#pragma unroll
        for (int e = 1; e < EZ_EXP; e++) mx = fmaxf(mx, logits[e]);
        float sc[EZ_EXP], s = 0.f;
#pragma unroll
        for (int e = 0; e < EZ_EXP; e++) { sc[e] = __expf(logits[e] - mx); s += sc[e]; }
        const float inv = 1.f / s;
        float bsc[EZ_EXP];
#pragma unroll
        for (int e = 0; e < EZ_EXP; e++) { sc[e] *= inv; bsc[e] = sc[e] + bias[e]; }

        int i1 = 0;
#pragma unroll
        for (int e = 1; e < EZ_EXP; e++) if (bsc[e] > bsc[i1]) i1 = e;
        int i2 = (i1 == 0) ? 1 : 0;
#pragma unroll
        for (int e = 0; e < EZ_EXP; e++) if (e != i1 && bsc[e] > bsc[i2]) i2 = e;

        const float w1 = sc[i1], w2v = sc[i2];
        g_top_idx[2 * t] = i1;  g_top_idx[2 * t + 1] = i2;
        g_top_w[2 * t] = w1;    g_top_w[2 * t + 1] = w2v;
        float zs = 0.f;
        if (i1 >= E_EXP) zs += w1;
        if (i2 >= E_EXP) zs += w2v;
        g_zero_scale[t] = zs;
    }
}

// ============================================================================
// parallel deterministic list build (proven)
// ============================================================================
__global__ void __launch_bounds__(256) count_kernel()
{
    const int e = blockIdx.x, j = blockIdx.y;
    const int tid = threadIdx.x, lane = tid & 31, w = tid >> 5;
    __shared__ int wsum[8];
    int c = 0;
#pragma unroll
    for (int it = 0; it < 4; it++)
        c += (g_top_idx[j * 1024 + it * 256 + tid] == e) ? 1 : 0;
#pragma unroll
    for (int off = 16; off; off >>= 1) c += __shfl_xor_sync(0xffffffffu, c, off);
    if (lane == 0) wsum[w] = c;
    __syncthreads();
    if (tid == 0) {
        int tot = 0;
#pragma unroll
        for (int i = 0; i < 8; i++) tot += wsum[i];
        g_blk[e][j] = tot;
    }
}

__global__ void __launch_bounds__(256) scatter_kernel()
{
    const int e = blockIdx.x, j = blockIdx.y;
    const int tid = threadIdx.x, lane = tid & 31, w = tid >> 5;
    __shared__ int warp_tot[8];
    __shared__ int s_base;

    if (tid == 0) {
        int base = 0, tot = 0;
#pragma unroll
        for (int i = 0; i < 16; i++) {
            const int v = g_blk[e][i];
            if (i < j) base += v;
            tot += v;
        }
        s_base = base;
        if (j == 0) g_counts[e] = tot;
    }
    __syncthreads();

#pragma unroll 1
    for (int it = 0; it < 4; it++) {
        const int slot = j * 1024 + it * 256 + tid;
        const int flag = (g_top_idx[slot] == e) ? 1 : 0;
        const unsigned bal = __ballot_sync(0xffffffffu, flag);
        const int pre = __popc(bal & ((1u << lane) - 1u));
        if (lane == 0) warp_tot[w] = __popc(bal);
        __syncthreads();
        int woff = 0;
        for (int i = 0; i < w; i++) woff += warp_tot[i];
        if (flag) g_rows[e * T_TOK + s_base + woff + pre] = slot;
        __syncthreads();
        if (tid == 0) {
            int tt = 0;
#pragma unroll
            for (int i = 0; i < 8; i++) tt += warp_tot[i];
            s_base += tt;
        }
        __syncthreads();
    }
}

// ============================================================================
// HMMA GEMMs, 1-term fp16. CTA tile 128(M) x 256(N), 8 warps (2Mx4N),
// warp tile 64x64 -> 16 MAC per ldsm-byte. K chunk 32, 4-stage cp.async.
// Smem/stage: A 128x80B + B 256x80B = 30720 B; 4 stages = 122880 B, 1 CTA/SM.
// ============================================================================
#define ROWB   80
#define AMATB  (128 * ROWB)          // 10240
#define BMATB  (256 * ROWB)          // 20480
#define STAGE  (AMATB + BMATB)       // 30720
#define NSTG   4
#define SMEM_DYN (NSTG * STAGE)      // 122880

// ---- up GEMM + SiLU: A = x(fp16), B = 256 interleaved gate/up rows. grid (E*64, 4)
__global__ void __launch_bounds__(256, 1) up_gemm_mma()
{
    const int e  = blockIdx.x >> 6;
    const int mt = blockIdx.x & 63;
    const int cnt = g_counts[e];
    const int m0 = mt * 128;
    if (m0 >= cnt) return;
    const int rcount = min(128, cnt - m0);
    const int ib = blockIdx.y * 128;          // intermediate-column base (128 per CTA)

    extern __shared__ char sm[];
    const u32 smu = smem_u32(sm);
    __shared__ int s_slot[128];
    __shared__ int s_tok[128];

    const int tid = threadIdx.x, lane = tid & 31, wid = tid >> 5;
    const int wm = wid >> 2, wn = wid & 3;

    if (tid < 128) {
        const int sl = g_rows[e * T_TOK + m0 + min(tid, rcount - 1)];
        s_slot[tid] = sl;
        s_tok[tid] = sl >> 1;
    }
    __syncthreads();

    // 6 cp.async descriptors/thread: A 512 chunks + B 1024 chunks, 16B each
    const char* srcs[6];
    u32 dsts[6];
#pragma unroll
    for (int t = 0; t < 6; t++) {
        const int idx = tid + t * 256;
        if (idx < 512) {
            const int rr = idx >> 2, ch = idx & 3;
            dsts[t] = (u32)(rr * ROWB + ch * 16);
            srcs[t] = (const char*)(g_xh + (size_t)s_tok[rr] * H_DIM + ch * 8);
        } else {
            const int j = idx - 512, rr = j >> 2, ch = j & 3;
            dsts[t] = (u32)(AMATB + rr * ROWB + ch * 16);
            const int wrow = (rr & 1) ? (512 + ib + (rr >> 1)) : (ib + (rr >> 1));
            srcs[t] = (const char*)(g_w13h + ((size_t)e * 1024 + wrow) * H_DIM + ch * 8);
        }
    }

    float acc[4][8][4];
#pragma unroll
    for (int i = 0; i < 4; i++)
#pragma unroll
        for (int j = 0; j < 8; j++)
#pragma unroll
            for (int q = 0; q < 4; q++) acc[i][j][q] = 0.f;

#pragma unroll
    for (int s = 0; s < 3; s++) {
#pragma unroll
        for (int t = 0; t < 6; t++) CPA16(smu + s * STAGE + dsts[t], srcs[t] + (size_t)s * 64);
        CPCOMMIT();
    }

    const u32 lrow = (u32)(lane & 15) * ROWB + (u32)((lane >> 4) << 4);

#pragma unroll 1
    for (int c = 0; c < 32; c++) {
        const int p = c & 3;
        CPWAIT2();
        __syncthreads();
        if (c + 3 < 32) {
            const u32 sb = smu + ((c + 3) & 3) * STAGE;
            const size_t go = (size_t)(c + 3) * 64;
#pragma unroll
            for (int t = 0; t < 6; t++) CPA16(sb + dsts[t], srcs[t] + go);
        }
        CPCOMMIT();

        const u32 aB = smu + p * STAGE + (u32)(wm * 64) * ROWB + lrow;
        const u32 bB = smu + p * STAGE + AMATB + (u32)(wn * 64) * ROWB + lrow;
#pragma unroll
        for (int kk = 0; kk < 2; kk++) {
            const u32 ko = kk * 32;
            u32 a[4][4], b[4][4];
#pragma unroll
            for (int mi = 0; mi < 4; mi++)
                ldsm4(a[mi][0], a[mi][1], a[mi][2], a[mi][3], aB + mi * 16 * ROWB + ko);
#pragma unroll
            for (int g = 0; g < 4; g++)
                ldsm4(b[g][0], b[g][1], b[g][2], b[g][3], bB + g * 16 * ROWB + ko);
#pragma unroll
            for (int mi = 0; mi < 4; mi++)
#pragma unroll
                for (int nj = 0; nj < 8; nj++) {
                    const int g = nj >> 1, o = nj & 1;
                    mma_f16(acc[mi][nj], a[mi], b[g][o], b[g][o + 2]);
                }
        }
    }

    // ---- epilogue: silu(gate)*up -> smem fp16 (128 x 128 cols), coalesced out
    CPWAIT0();
    __syncthreads();
    __half* sact = (__half*)sm;               // stride 136 halves (272 B)
    const int qr = lane >> 2, qc = lane & 3;
#pragma unroll
    for (int mi = 0; mi < 4; mi++) {
        const int r0 = wm * 64 + mi * 16 + qr;
#pragma unroll
        for (int nj = 0; nj < 8; nj++) {
            const int col = wn * 32 + nj * 4 + qc;   // intermediate col within 128
            const float* a4 = acc[mi][nj];
            {
                const float g = a4[0], u = a4[1];
                sact[r0 * 136 + col] = __float2half_rn(g / (1.f + __expf(-g)) * u);
            }
            {
                const float g = a4[2], u = a4[3];
                sact[(r0 + 8) * 136 + col] = __float2half_rn(g / (1.f + __expf(-g)) * u);
            }
        }
    }
    __syncthreads();
    {
        const int r = tid >> 1, part = tid & 1;
        if (r < rcount) {
            const uint4* src = (const uint4*)((const char*)sm + r * 272 + part * 128);
            uint4* dst = (uint4*)(g_acth + (size_t)s_slot[r] * I_DIM + ib + part * 64);
#pragma unroll
            for (int i = 0; i < 8; i++) dst[i] = src[i];
        }
    }
}

// ---- down GEMM: A = act(fp16), B = w2 (256 H rows). K=512. grid (E*64, 4) ----
__global__ void __launch_bounds__(256, 1) down_gemm_mma()
{
    const int e  = blockIdx.x >> 6;
    const int mt = blockIdx.x & 63;
    const int cnt = g_counts[e];
    const int m0 = mt * 128;
    if (m0 >= cnt) return;
    const int rcount = min(128, cnt - m0);
    const int hb = blockIdx.y * 256;

    extern __shared__ char sm[];
    const u32 smu = smem_u32(sm);
    __shared__ int   s_slot[128];
    __shared__ float s_wt[128];

    const int tid = threadIdx.x, lane = tid & 31, wid = tid >> 5;
    const int wm = wid >> 2, wn = wid & 3;

    if (tid < 128) {
        const int sl = g_rows[e * T_TOK + m0 + min(tid, rcount - 1)];
        s_slot[tid] = sl;
        s_wt[tid] = g_top_w[sl] * SCALE_F;
    }
    __syncthreads();

    const char* srcs[6];
    u32 dsts[6];
#pragma unroll
    for (int t = 0; t < 6; t++) {
        const int idx = tid + t * 256;
        if (idx < 512) {
            const int rr = idx >> 2, ch = idx & 3;
            dsts[t] = (u32)(rr * ROWB + ch * 16);
            srcs[t] = (const char*)(g_acth + (size_t)s_slot[rr] * I_DIM + ch * 8);
        } else {
            const int j = idx - 512, rr = j >> 2, ch = j & 3;
            dsts[t] = (u32)(AMATB + rr * ROWB + ch * 16);
            srcs[t] = (const char*)(g_w2h + ((size_t)e * H_DIM + hb + rr) * I_DIM + ch * 8);
        }
    }

    float acc[4][8][4];
#pragma unroll
    for (int i = 0; i < 4; i++)
#pragma unroll
        for (int j = 0; j < 8; j++)
#pragma unroll
            for (int q = 0; q < 4; q++) acc[i][j][q] = 0.f;

#pragma unroll
    for (int s = 0; s < 3; s++) {
#pragma unroll
        for (int t = 0; t < 6; t++) CPA16(smu + s * STAGE + dsts[t], srcs[t] + (size_t)s * 64);
        CPCOMMIT();
    }

    const u32 lrow = (u32)(lane & 15) * ROWB + (u32)((lane >> 4) << 4);

#pragma unroll 1
    for (int c = 0; c < 16; c++) {
        const int p = c & 3;
        CPWAIT2();
        __syncthreads();
        if (c + 3 < 16) {
            const u32 sb = smu + ((c + 3) & 3) * STAGE;
            const size_t go = (size_t)(c + 3) * 64;
#pragma unroll
            for (int t = 0; t < 6; t++) CPA16(sb + dsts[t], srcs[t] + go);
        }
        CPCOMMIT();

        const u32 aB = smu + p * STAGE + (u32)(wm * 64) * ROWB + lrow;
        const u32 bB = smu + p * STAGE + AMATB + (u32)(wn * 64) * ROWB + lrow;
#pragma unroll
        for (int kk = 0; kk < 2; kk++) {
            const u32 ko = kk * 32;
            u32 a[4][4], b[4][4];
#pragma unroll
            for (int mi = 0; mi < 4; mi++)
                ldsm4(a[mi][0], a[mi][1], a[mi][2], a[mi][3], aB + mi * 16 * ROWB + ko);
#pragma unroll
            for (int g = 0; g < 4; g++)
                ldsm4(b[g][0], b[g][1], b[g][2], b[g][3], bB + g * 16 * ROWB + ko);
#pragma unroll
            for (int mi = 0; mi < 4; mi++)
#pragma unroll
                for (int nj = 0; nj < 8; nj++) {
                    const int g = nj >> 1, o = nj & 1;
                    mma_f16(acc[mi][nj], a[mi], b[g][o], b[g][o + 2]);
                }
        }
    }

    // ---- epilogue: scale, stage fp16 (128 x 256 cols), coalesced out ----
    CPWAIT0();
    __syncthreads();
    __half* sy = (__half*)sm;                 // stride 264 halves (528 B)
    const int qr = lane >> 2, qc = lane & 3;
#pragma unroll
    for (int mi = 0; mi < 4; mi++) {
        const int r0 = wm * 64 + mi * 16 + qr;
        const float w0 = s_wt[r0], w1 = s_wt[r0 + 8];
#pragma unroll
        for (int nj = 0; nj < 8; nj++) {
            const int col = wn * 64 + nj * 8 + 2 * qc;
            const float* a4 = acc[mi][nj];
            *(__half2*)(sy + r0 * 264 + col) =
                __halves2half2(__float2half_rn(w0 * a4[0]), __float2half_rn(w0 * a4[1]));
            *(__half2*)(sy + (r0 + 8) * 264 + col) =
                __halves2half2(__float2half_rn(w1 * a4[2]), __float2half_rn(w1 * a4[3]));
        }
    }
    __syncthreads();
    {
        const int r = tid >> 1, part = tid & 1;
        if (r < rcount) {
            const uint4* src = (const uint4*)((const char*)sm + r * 528 + part * 256);
            uint4* dst = (uint4*)(g_yh + (size_t)s_slot[r] * H_DIM + hb + part * 128);
#pragma unroll
            for (int i = 0; i < 16; i++) dst[i] = src[i];
        }
    }
}

// ============================================================================
// finalize: out = zero_scale*x + slot sums (fp16 y)
// ============================================================================
__global__ void __launch_bounds__(256) finalize_kernel(
    const float* __restrict__ x, float* __restrict__ out)
{
    const int t = blockIdx.x;
    const float zs = g_zero_scale[t];
    const bool r0 = g_top_idx[2 * t]     < E_EXP;
    const bool r1 = g_top_idx[2 * t + 1] < E_EXP;
    const int h = threadIdx.x * 4;

    float4 xv = *(const float4*)(x + (size_t)t * H_DIM + h);
    float4 o;
    o.x = zs * xv.x; o.y = zs * xv.y; o.z = zs * xv.z; o.w = zs * xv.w;
    if (r0) {
        const __half2* y = (const __half2*)(g_yh + (size_t)(2 * t) * H_DIM + h);
        const float2 a = __half22float2(y[0]), b = __half22float2(y[1]);
        o.x += a.x; o.y += a.y; o.z += b.x; o.w += b.y;
    }
    if (r1) {
        const __half2* y = (const __half2*)(g_yh + (size_t)(2 * t + 1) * H_DIM + h);
        const float2 a = __half22float2(y[0]), b = __half22float2(y[1]);
        o.x += a.x; o.y += a.y; o.z += b.x; o.w += b.y;
    }
    *(float4*)(out + (size_t)t * H_DIM + h) = o;
}

// ============================================================================
// launch
// ============================================================================
extern "C" void kernel_launch(void* const* d_in, const int* in_sizes, int n_in,
                              void* d_out, int out_size)
{
    const float* x    = (const float*)d_in[0];
    const float* rw   = (const float*)d_in[1];
    const float* bias = (const float*)d_in[2];
    const float* w13  = (const float*)d_in[3];
    const float* w2   = (const float*)d_in[4];
    float* out = (float*)d_out;

    cudaFuncSetAttribute(up_gemm_mma,   cudaFuncAttributeMaxDynamicSharedMemorySize, SMEM_DYN);
    cudaFuncSetAttribute(down_gemm_mma, cudaFuncAttributeMaxDynamicSharedMemorySize, SMEM_DYN);

    cvt_w_kernel<<<(int)((W13_ELEMS + (size_t)E_EXP * H_DIM * I_DIM) / 1024), 256>>>(w13, w2);
    router_kernel<<<T_TOK / 8, 256>>>(x, rw, bias);

    dim3 gl(E_EXP, 16);
    count_kernel<<<gl, 256>>>();
    scatter_kernel<<<gl, 256>>>();

    dim3 gu(E_EXP * 64, 4);
    up_gemm_mma<<<gu, 256, SMEM_DYN>>>();

    dim3 gd(E_EXP * 64, 4);
    down_gemm_mma<<<gd, 256, SMEM_DYN>>>();

    finalize_kernel<<<T_TOK, 256>>>(x, out);
}

// round 9
// speedup vs baseline: 1.1670x; 1.1670x over previous
#include <cuda_runtime.h>
#include <cuda_fp16.h>
#include <cstdint>

#define T_TOK   8192
#define H_DIM   1024
#define I_DIM   512
#define E_EXP   8
#define EZ_EXP  12
#define SCALE_F 2.5f

typedef unsigned int u32;
typedef unsigned long long u64;

// ---------------- scratch (device globals; no allocation) ----------------
__device__ int    g_top_idx[T_TOK * 2];
__device__ float  g_top_w[T_TOK * 2];
__device__ float  g_zero_scale[T_TOK];
__device__ int    g_counts[E_EXP];
__device__ int    g_blk[E_EXP][16];
__device__ int    g_rows[E_EXP * T_TOK];
__device__ __half g_xh[(size_t)T_TOK * H_DIM];
__device__ __half g_w13h[(size_t)E_EXP * 2 * I_DIM * H_DIM];
__device__ __half g_w2h[(size_t)E_EXP * H_DIM * I_DIM];
__device__ __half g_acth[(size_t)T_TOK * 2 * I_DIM];
__device__ __half g_yh[(size_t)T_TOK * 2 * H_DIM];

// ---------------- helpers ----------------
__device__ __forceinline__ u32 smem_u32(const void* p) {
    u32 a;
    asm("{ .reg .u64 t; cvta.to.shared.u64 t, %1; cvt.u32.u64 %0, t; }" : "=r"(a) : "l"(p));
    return a;
}

#define CPA16(dst, src) \
    asm volatile("{.reg .u64 g; cvta.to.global.u64 g, %1; cp.async.cg.shared.global [%0], [g], 16;}\n" \
                 :: "r"((u32)(dst)), "l"(src) : "memory")
#define CPCOMMIT() asm volatile("cp.async.commit_group;" ::: "memory")
#define CPWAIT2()  asm volatile("cp.async.wait_group 2;" ::: "memory")

__device__ __forceinline__ void ldsm4(u32& r0, u32& r1, u32& r2, u32& r3, u32 addr) {
    asm volatile("ldmatrix.sync.aligned.m8n8.x4.shared.b16 {%0,%1,%2,%3}, [%4];"
                 : "=r"(r0), "=r"(r1), "=r"(r2), "=r"(r3) : "r"(addr));
}

__device__ __forceinline__ void mma_f16(float* d, const u32* a, u32 b0, u32 b1) {
    asm volatile("mma.sync.aligned.m16n8k16.row.col.f32.f16.f16.f32 "
        "{%0,%1,%2,%3}, {%4,%5,%6,%7}, {%8,%9}, {%0,%1,%2,%3};"
        : "+f"(d[0]), "+f"(d[1]), "+f"(d[2]), "+f"(d[3])
        : "r"(a[0]), "r"(a[1]), "r"(a[2]), "r"(a[3]), "r"(b0), "r"(b1));
}

// ============================================================================
// weight conversion (one-time)
// ============================================================================
#define W13_ELEMS ((size_t)E_EXP * 2 * I_DIM * H_DIM)
__global__ void __launch_bounds__(256) cvt_w_kernel(
    const float* __restrict__ w13, const float* __restrict__ w2)
{
    const size_t gid = (size_t)blockIdx.x * 256 + threadIdx.x;
    const float* src; __half* dst; size_t off;
    if (gid < W13_ELEMS / 4) { src = w13; dst = g_w13h; off = gid * 4; }
    else { src = w2; dst = g_w2h; off = (gid - W13_ELEMS / 4) * 4; }
    const float4 v = *(const float4*)(src + off);
    *(__half2*)(dst + off)     = __halves2half2(__float2half_rn(v.x), __float2half_rn(v.y));
    *(__half2*)(dst + off + 2) = __halves2half2(__float2half_rn(v.z), __float2half_rn(v.w));
}

// ============================================================================
// router + fused x->fp16 conversion. 2 tokens per warp (halved LDS traffic).
// block = 256 threads = 8 warps = 16 tokens; grid = 512.
// ============================================================================
__global__ void __launch_bounds__(256) router_kernel(
    const float* __restrict__ x, const float* __restrict__ rw, const float* __restrict__ bias)
{
    __shared__ float srw[EZ_EXP * H_DIM];
    const int tid = threadIdx.x;
    for (int i = tid; i < EZ_EXP * H_DIM; i += 256) srw[i] = rw[i];
    __syncthreads();

    const int warp = tid >> 5, lane = tid & 31;
    const int t0 = blockIdx.x * 16 + warp * 2;
    const float* xr0 = x + (size_t)t0 * H_DIM;
    const float* xr1 = x + (size_t)(t0 + 1) * H_DIM;

    float xv0[32], xv1[32];
#pragma unroll
    for (int j = 0; j < 32; j++) { xv0[j] = xr0[lane + 32 * j]; xv1[j] = xr1[lane + 32 * j]; }

    __half* xh0 = g_xh + (size_t)t0 * H_DIM;
    __half* xh1 = g_xh + (size_t)(t0 + 1) * H_DIM;
#pragma unroll
    for (int j = 0; j < 32; j++) {
        xh0[lane + 32 * j] = __float2half_rn(xv0[j]);
        xh1[lane + 32 * j] = __float2half_rn(xv1[j]);
    }

    float lg[2][EZ_EXP];
#pragma unroll
    for (int e = 0; e < EZ_EXP; e++) {
        const float* wr = srw + e * H_DIM;
        float a0 = 0.f, a1 = 0.f;
#pragma unroll
        for (int j = 0; j < 32; j++) {
            const float w = wr[lane + 32 * j];
            a0 += xv0[j] * w;
            a1 += xv1[j] * w;
        }
#pragma unroll
        for (int off = 16; off; off >>= 1) {
            a0 += __shfl_xor_sync(0xffffffffu, a0, off);
            a1 += __shfl_xor_sync(0xffffffffu, a1, off);
        }
        lg[0][e] = a0; lg[1][e] = a1;
    }

    if (lane == 0) {
#pragma unroll
        for (int q = 0; q < 2; q++) {
            const int t = t0 + q;
            float mx = lg[q][0];
#pragma unroll
            for (int e = 1; e < EZ_EXP; e++) mx = fmaxf(mx, lg[q][e]);
            float sc[EZ_EXP], s = 0.f;
#pragma unroll
            for (int e = 0; e < EZ_EXP; e++) { sc[e] = __expf(lg[q][e] - mx); s += sc[e]; }
            const float inv = 1.f / s;
            float bsc[EZ_EXP];
#pragma unroll
            for (int e = 0; e < EZ_EXP; e++) { sc[e] *= inv; bsc[e] = sc[e] + bias[e]; }

            int i1 = 0;
#pragma unroll
            for (int e = 1; e < EZ_EXP; e++) if (bsc[e] > bsc[i1]) i1 = e;
            int i2 = (i1 == 0) ? 1 : 0;
#pragma unroll
            for (int e = 0; e < EZ_EXP; e++) if (e != i1 && bsc[e] > bsc[i2]) i2 = e;

            const float w1 = sc[i1], w2v = sc[i2];
            g_top_idx[2 * t] = i1;  g_top_idx[2 * t + 1] = i2;
            g_top_w[2 * t] = w1;    g_top_w[2 * t + 1] = w2v;
            float zs = 0.f;
            if (i1 >= E_EXP) zs += w1;
            if (i2 >= E_EXP) zs += w2v;
            g_zero_scale[t] = zs;
        }
    }
}

// ============================================================================
// parallel deterministic list build (proven)
// ============================================================================
__global__ void __launch_bounds__(256) count_kernel()
{
    const int e = blockIdx.x, j = blockIdx.y;
    const int tid = threadIdx.x, lane = tid & 31, w = tid >> 5;
    __shared__ int wsum[8];
    int c = 0;
#pragma unroll
    for (int it = 0; it < 4; it++)
        c += (g_top_idx[j * 1024 + it * 256 + tid] == e) ? 1 : 0;
#pragma unroll
    for (int off = 16; off; off >>= 1) c += __shfl_xor_sync(0xffffffffu, c, off);
    if (lane == 0) wsum[w] = c;
    __syncthreads();
    if (tid == 0) {
        int tot = 0;
#pragma unroll
        for (int i = 0; i < 8; i++) tot += wsum[i];
        g_blk[e][j] = tot;
    }
}

__global__ void __launch_bounds__(256) scatter_kernel()
{
    const int e = blockIdx.x, j = blockIdx.y;
    const int tid = threadIdx.x, lane = tid & 31, w = tid >> 5;
    __shared__ int warp_tot[8];
    __shared__ int s_base;

    if (tid == 0) {
        int base = 0, tot = 0;
#pragma unroll
        for (int i = 0; i < 16; i++) {
            const int v = g_blk[e][i];
            if (i < j) base += v;
            tot += v;
        }
        s_base = base;
        if (j == 0) g_counts[e] = tot;
    }
    __syncthreads();

#pragma unroll 1
    for (int it = 0; it < 4; it++) {
        const int slot = j * 1024 + it * 256 + tid;
        const int flag = (g_top_idx[slot] == e) ? 1 : 0;
        const unsigned bal = __ballot_sync(0xffffffffu, flag);
        const int pre = __popc(bal & ((1u << lane) - 1u));
        if (lane == 0) warp_tot[w] = __popc(bal);
        __syncthreads();
        int woff = 0;
        for (int i = 0; i < w; i++) woff += warp_tot[i];
        if (flag) g_rows[e * T_TOK + s_base + woff + pre] = slot;
        __syncthreads();
        if (tid == 0) {
            int tt = 0;
#pragma unroll
            for (int i = 0; i < 8; i++) tt += warp_tot[i];
            s_base += tt;
        }
        __syncthreads();
    }
}

// ============================================================================
// HMMA GEMMs — round-6 champion config, byte-identical mainloops.
// CTA 128x128, 8 warps (2Mx4N), warp tile 64x32, K chunk 32, NSTG=4.
// ============================================================================
#define ROWB   80
#define MATB   (128 * ROWB)        // 10240
#define STAGE  (2 * MATB)          // 20480
#define NSTG   4
#define SMEM_DYN (NSTG * STAGE)    // 81920

// ---- up GEMM + SiLU: A = x(fp16), B = w13 interleaved gate/up. grid (E*64, 8)
__global__ void __launch_bounds__(256, 2) up_gemm_mma()
{
    const int e  = blockIdx.x >> 6;
    const int mt = blockIdx.x & 63;
    const int cnt = g_counts[e];
    const int m0 = mt * 128;
    if (m0 >= cnt) return;
    const int rcount = min(128, cnt - m0);
    const int ib = blockIdx.y * 64;

    extern __shared__ char sm[];
    const u32 smu = smem_u32(sm);
    __shared__ int s_slot[128];
    __shared__ int s_tok[128];

    const int tid = threadIdx.x, lane = tid & 31, wid = tid >> 5;
    const int wm = wid >> 2, wn = wid & 3;

    if (tid < 128) {
        const int sl = g_rows[e * T_TOK + m0 + min(tid, rcount - 1)];
        s_slot[tid] = sl;
        s_tok[tid] = sl >> 1;
    }
    __syncthreads();

    const char* srcs[4];
    u32 dsts[4];
#pragma unroll
    for (int t = 0; t < 4; t++) {
        const int idx = tid + t * 256;
        const int mat = idx >> 9, rr = (idx >> 2) & 127, ch = idx & 3;
        dsts[t] = (u32)(mat * MATB + rr * ROWB + ch * 16);
        if (mat == 0) srcs[t] = (const char*)(g_xh + (size_t)s_tok[rr] * H_DIM + ch * 8);
        else {
            const int wrow = (rr & 1) ? (512 + ib + (rr >> 1)) : (ib + (rr >> 1));
            srcs[t] = (const char*)(g_w13h + ((size_t)e * 1024 + wrow) * H_DIM + ch * 8);
        }
    }

    float acc[4][4][4];
#pragma unroll
    for (int i = 0; i < 4; i++)
#pragma unroll
        for (int j = 0; j < 4; j++)
#pragma unroll
            for (int q = 0; q < 4; q++) acc[i][j][q] = 0.f;

#pragma unroll
    for (int s = 0; s < 3; s++) {
#pragma unroll
        for (int t = 0; t < 4; t++) CPA16(smu + s * STAGE + dsts[t], srcs[t] + (size_t)s * 64);
        CPCOMMIT();
    }

    const u32 lrow = (u32)(lane & 15) * ROWB + (u32)((lane >> 4) << 4);

#pragma unroll 1
    for (int c = 0; c < 32; c++) {
        const int p = c & 3;
        CPWAIT2();
        __syncthreads();
        if (c + 3 < 32) {
            const u32 sb = smu + ((c + 3) & 3) * STAGE;
            const size_t go = (size_t)(c + 3) * 64;
#pragma unroll
            for (int t = 0; t < 4; t++) CPA16(sb + dsts[t], srcs[t] + go);
        }
        CPCOMMIT();

        const u32 aB = smu + p * STAGE + (u32)(wm * 64) * ROWB + lrow;
        const u32 bB = smu + p * STAGE + MATB + (u32)(wn * 32) * ROWB + lrow;
#pragma unroll
        for (int kk = 0; kk < 2; kk++) {
            const u32 ko = kk * 32;
            u32 a[4][4], b[2][4];
#pragma unroll
            for (int mi = 0; mi < 4; mi++)
                ldsm4(a[mi][0], a[mi][1], a[mi][2], a[mi][3], aB + mi * 16 * ROWB + ko);
            ldsm4(b[0][0], b[0][1], b[0][2], b[0][3], bB + ko);
            ldsm4(b[1][0], b[1][1], b[1][2], b[1][3], bB + 16 * ROWB + ko);
#pragma unroll
            for (int mi = 0; mi < 4; mi++)
#pragma unroll
                for (int nj = 0; nj < 4; nj++) {
                    const int g = nj >> 1, o = nj & 1;
                    mma_f16(acc[mi][nj], a[mi], b[g][o], b[g][o + 2]);
                }
        }
    }

    // epilogue (round-6 style: direct stores)
    const int qr = lane >> 2, qc = lane & 3;
#pragma unroll
    for (int mi = 0; mi < 4; mi++) {
        const int mlo = wm * 64 + mi * 16 + qr;
#pragma unroll
        for (int nj = 0; nj < 4; nj++) {
            const int icol = ib + wn * 16 + nj * 4 + qc;
            const float* a4 = acc[mi][nj];
            if (mlo < rcount) {
                const float g = a4[0], u = a4[1];
                g_acth[(size_t)s_slot[mlo] * I_DIM + icol] =
                    __float2half_rn(g / (1.f + __expf(-g)) * u);
            }
            if (mlo + 8 < rcount) {
                const float g = a4[2], u = a4[3];
                g_acth[(size_t)s_slot[mlo + 8] * I_DIM + icol] =
                    __float2half_rn(g / (1.f + __expf(-g)) * u);
            }
        }
    }
}

// ---- down GEMM: A = act(fp16), B = w2. K=512 (16 chunks). grid (E*64, 8) ----
__global__ void __launch_bounds__(256, 2) down_gemm_mma()
{
    const int e  = blockIdx.x >> 6;
    const int mt = blockIdx.x & 63;
    const int cnt = g_counts[e];
    const int m0 = mt * 128;
    if (m0 >= cnt) return;
    const int rcount = min(128, cnt - m0);
    const int hb = blockIdx.y * 128;

    extern __shared__ char sm[];
    const u32 smu = smem_u32(sm);
    __shared__ int   s_slot[128];
    __shared__ float s_wt[128];

    const int tid = threadIdx.x, lane = tid & 31, wid = tid >> 5;
    const int wm = wid >> 2, wn = wid & 3;

    if (tid < 128) {
        const int sl = g_rows[e * T_TOK + m0 + min(tid, rcount - 1)];
        s_slot[tid] = sl;
        s_wt[tid] = g_top_w[sl] * SCALE_F;
    }
    __syncthreads();

    const char* srcs[4];
    u32 dsts[4];
#pragma unroll
    for (int t = 0; t < 4; t++) {
        const int idx = tid + t * 256;
        const int mat = idx >> 9, rr = (idx >> 2) & 127, ch = idx & 3;
        dsts[t] = (u32)(mat * MATB + rr * ROWB + ch * 16);
        if (mat == 0) srcs[t] = (const char*)(g_acth + (size_t)s_slot[rr] * I_DIM + ch * 8);
        else srcs[t] = (const char*)(g_w2h + ((size_t)e * H_DIM + hb + rr) * I_DIM + ch * 8);
    }

    float acc[4][4][4];
#pragma unroll
    for (int i = 0; i < 4; i++)
#pragma unroll
        for (int j = 0; j < 4; j++)
#pragma unroll
            for (int q = 0; q < 4; q++) acc[i][j][q] = 0.f;

#pragma unroll
    for (int s = 0; s < 3; s++) {
#pragma unroll
        for (int t = 0; t < 4; t++) CPA16(smu + s * STAGE + dsts[t], srcs[t] + (size_t)s * 64);
        CPCOMMIT();
    }

    const u32 lrow = (u32)(lane & 15) * ROWB + (u32)((lane >> 4) << 4);

#pragma unroll 1
    for (int c = 0; c < 16; c++) {
        const int p = c & 3;
        CPWAIT2();
        __syncthreads();
        if (c + 3 < 16) {
            const u32 sb = smu + ((c + 3) & 3) * STAGE;
            const size_t go = (size_t)(c + 3) * 64;
#pragma unroll
            for (int t = 0; t < 4; t++) CPA16(sb + dsts[t], srcs[t] + go);
        }
        CPCOMMIT();

        const u32 aB = smu + p * STAGE + (u32)(wm * 64) * ROWB + lrow;
        const u32 bB = smu + p * STAGE + MATB + (u32)(wn * 32) * ROWB + lrow;
#pragma unroll
        for (int kk = 0; kk < 2; kk++) {
            const u32 ko = kk * 32;
            u32 a[4][4], b[2][4];
#pragma unroll
            for (int mi = 0; mi < 4; mi++)
                ldsm4(a[mi][0], a[mi][1], a[mi][2], a[mi][3], aB + mi * 16 * ROWB + ko);
            ldsm4(b[0][0], b[0][1], b[0][2], b[0][3], bB + ko);
            ldsm4(b[1][0], b[1][1], b[1][2], b[1][3], bB + 16 * ROWB + ko);
#pragma unroll
            for (int mi = 0; mi < 4; mi++)
#pragma unroll
                for (int nj = 0; nj < 4; nj++) {
                    const int g = nj >> 1, o = nj & 1;
                    mma_f16(acc[mi][nj], a[mi], b[g][o], b[g][o + 2]);
                }
        }
    }

    // epilogue (round-6 pattern, fp16 stores)
    const int qr = lane >> 2, qc = lane & 3;
#pragma unroll
    for (int mi = 0; mi < 4; mi++) {
        const int mlo = wm * 64 + mi * 16 + qr;
#pragma unroll
        for (int nj = 0; nj < 4; nj++) {
            const int n0 = hb + wn * 32 + nj * 8 + 2 * qc;
            const float* a4 = acc[mi][nj];
            if (mlo < rcount) {
                const float wt = s_wt[mlo];
                *(__half2*)(g_yh + (size_t)s_slot[mlo] * H_DIM + n0) =
                    __halves2half2(__float2half_rn(wt * a4[0]), __float2half_rn(wt * a4[1]));
            }
            if (mlo + 8 < rcount) {
                const float wt = s_wt[mlo + 8];
                *(__half2*)(g_yh + (size_t)s_slot[mlo + 8] * H_DIM + n0) =
                    __halves2half2(__float2half_rn(wt * a4[2]), __float2half_rn(wt * a4[3]));
            }
        }
    }
}

// ============================================================================
// finalize: out = zero_scale*x + slot sums (fp16 y)
// ============================================================================
__global__ void __launch_bounds__(256) finalize_kernel(
    const float* __restrict__ x, float* __restrict__ out)
{
    const int t = blockIdx.x;
    const float zs = g_zero_scale[t];
    const bool r0 = g_top_idx[2 * t]     < E_EXP;
    const bool r1 = g_top_idx[2 * t + 1] < E_EXP;
    const int h = threadIdx.x * 4;

    float4 xv = *(const float4*)(x + (size_t)t * H_DIM + h);
    float4 o;
    o.x = zs * xv.x; o.y = zs * xv.y; o.z = zs * xv.z; o.w = zs * xv.w;
    if (r0) {
        const __half2* y = (const __half2*)(g_yh + (size_t)(2 * t) * H_DIM + h);
        const float2 a = __half22float2(y[0]), b = __half22float2(y[1]);
        o.x += a.x; o.y += a.y; o.z += b.x; o.w += b.y;
    }
    if (r1) {
        const __half2* y = (const __half2*)(g_yh + (size_t)(2 * t + 1) * H_DIM + h);
        const float2 a = __half22float2(y[0]), b = __half22float2(y[1]);
        o.x += a.x; o.y += a.y; o.z += b.x; o.w += b.y;
    }
    *(float4*)(out + (size_t)t * H_DIM + h) = o;
}

// ============================================================================
// launch
// ============================================================================
extern "C" void kernel_launch(void* const* d_in, const int* in_sizes, int n_in,
                              void* d_out, int out_size)
{
    const float* x    = (const float*)d_in[0];
    const float* rw   = (const float*)d_in[1];
    const float* bias = (const float*)d_in[2];
    const float* w13  = (const float*)d_in[3];
    const float* w2   = (const float*)d_in[4];
    float* out = (float*)d_out;

    cudaFuncSetAttribute(up_gemm_mma,   cudaFuncAttributeMaxDynamicSharedMemorySize, SMEM_DYN);
    cudaFuncSetAttribute(down_gemm_mma, cudaFuncAttributeMaxDynamicSharedMemorySize, SMEM_DYN);

    cvt_w_kernel<<<(int)((W13_ELEMS + (size_t)E_EXP * H_DIM * I_DIM) / 1024), 256>>>(w13, w2);
    router_kernel<<<T_TOK / 16, 256>>>(x, rw, bias);

    dim3 gl(E_EXP, 16);
    count_kernel<<<gl, 256>>>();
    scatter_kernel<<<gl, 256>>>();

    dim3 gu(E_EXP * 64, 8);
    up_gemm_mma<<<gu, 256, SMEM_DYN>>>();

    dim3 gd(E_EXP * 64, 8);
    down_gemm_mma<<<gd, 256, SMEM_DYN>>>();

    finalize_kernel<<<T_TOK, 256>>>(x, out);
}

// round 10
// speedup vs baseline: 1.1862x; 1.0165x over previous
#include <cuda_runtime.h>
#include <cuda_fp16.h>
#include <cstdint>

#define T_TOK   8192
#define H_DIM   1024
#define I_DIM   512
#define E_EXP   8
#define EZ_EXP  12
#define SCALE_F 2.5f

typedef unsigned int u32;
typedef unsigned long long u64;

// ---------------- scratch (device globals; no allocation) ----------------
__device__ int    g_top_idx[T_TOK * 2];
__device__ float  g_top_w[T_TOK * 2];
__device__ float  g_zero_scale[T_TOK];
__device__ int    g_counts[E_EXP];
__device__ int    g_blk[E_EXP][16];
__device__ int    g_rows[E_EXP * T_TOK];
__device__ __half g_xh[(size_t)T_TOK * H_DIM];
__device__ __half g_w13h[(size_t)E_EXP * 2 * I_DIM * H_DIM];
__device__ __half g_w2h[(size_t)E_EXP * H_DIM * I_DIM];
__device__ __half g_acth[(size_t)T_TOK * 2 * I_DIM];
__device__ __half g_yh[(size_t)T_TOK * 2 * H_DIM];

// ---------------- helpers ----------------
__device__ __forceinline__ u32 smem_u32(const void* p) {
    u32 a;
    asm("{ .reg .u64 t; cvta.to.shared.u64 t, %1; cvt.u32.u64 %0, t; }" : "=r"(a) : "l"(p));
    return a;
}

#define CPA16(dst, src) \
    asm volatile("{.reg .u64 g; cvta.to.global.u64 g, %1; cp.async.cg.shared.global [%0], [g], 16;}\n" \
                 :: "r"((u32)(dst)), "l"(src) : "memory")
#define CPCOMMIT() asm volatile("cp.async.commit_group;" ::: "memory")
#define CPWAIT2()  asm volatile("cp.async.wait_group 2;" ::: "memory")

__device__ __forceinline__ void ldsm4(u32& r0, u32& r1, u32& r2, u32& r3, u32 addr) {
    asm volatile("ldmatrix.sync.aligned.m8n8.x4.shared.b16 {%0,%1,%2,%3}, [%4];"
                 : "=r"(r0), "=r"(r1), "=r"(r2), "=r"(r3) : "r"(addr));
}

__device__ __forceinline__ void mma_f16(float* d, const u32* a, u32 b0, u32 b1) {
    asm volatile("mma.sync.aligned.m16n8k16.row.col.f32.f16.f16.f32 "
        "{%0,%1,%2,%3}, {%4,%5,%6,%7}, {%8,%9}, {%0,%1,%2,%3};"
        : "+f"(d[0]), "+f"(d[1]), "+f"(d[2]), "+f"(d[3])
        : "r"(a[0]), "r"(a[1]), "r"(a[2]), "r"(a[3]), "r"(b0), "r"(b1));
}

// ============================================================================
// weight conversion (one-time) + zero g_blk for the router's atomic counting
// ============================================================================
#define W13_ELEMS ((size_t)E_EXP * 2 * I_DIM * H_DIM)
__global__ void __launch_bounds__(256) cvt_w_kernel(
    const float* __restrict__ w13, const float* __restrict__ w2)
{
    if (blockIdx.x == 0 && threadIdx.x < E_EXP * 16)
        ((int*)g_blk)[threadIdx.x] = 0;

    const size_t gid = (size_t)blockIdx.x * 256 + threadIdx.x;
    const float* src; __half* dst; size_t off;
    if (gid < W13_ELEMS / 4) { src = w13; dst = g_w13h; off = gid * 4; }
    else { src = w2; dst = g_w2h; off = (gid - W13_ELEMS / 4) * 4; }
    const float4 v = *(const float4*)(src + off);
    *(__half2*)(dst + off)     = __halves2half2(__float2half_rn(v.x), __float2half_rn(v.y));
    *(__half2*)(dst + off + 2) = __halves2half2(__float2half_rn(v.z), __float2half_rn(v.w));
}

// ============================================================================
// router + fused x->fp16 conversion + fused per-chunk expert counting.
// 2 tokens per warp; block = 16 tokens = 32 slots, all in chunk blockIdx.x>>5.
// ============================================================================
__global__ void __launch_bounds__(256) router_kernel(
    const float* __restrict__ x, const float* __restrict__ rw, const float* __restrict__ bias)
{
    __shared__ float srw[EZ_EXP * H_DIM];
    const int tid = threadIdx.x;
    for (int i = tid; i < EZ_EXP * H_DIM; i += 256) srw[i] = rw[i];
    __syncthreads();

    const int warp = tid >> 5, lane = tid & 31;
    const int t0 = blockIdx.x * 16 + warp * 2;
    const int chunk = blockIdx.x >> 5;
    const float* xr0 = x + (size_t)t0 * H_DIM;
    const float* xr1 = x + (size_t)(t0 + 1) * H_DIM;

    float xv0[32], xv1[32];
#pragma unroll
    for (int j = 0; j < 32; j++) { xv0[j] = xr0[lane + 32 * j]; xv1[j] = xr1[lane + 32 * j]; }

    __half* xh0 = g_xh + (size_t)t0 * H_DIM;
    __half* xh1 = g_xh + (size_t)(t0 + 1) * H_DIM;
#pragma unroll
    for (int j = 0; j < 32; j++) {
        xh0[lane + 32 * j] = __float2half_rn(xv0[j]);
        xh1[lane + 32 * j] = __float2half_rn(xv1[j]);
    }

    float lg[2][EZ_EXP];
#pragma unroll
    for (int e = 0; e < EZ_EXP; e++) {
        const float* wr = srw + e * H_DIM;
        float a0 = 0.f, a1 = 0.f;
#pragma unroll
        for (int j = 0; j < 32; j++) {
            const float w = wr[lane + 32 * j];
            a0 += xv0[j] * w;
            a1 += xv1[j] * w;
        }
#pragma unroll
        for (int off = 16; off; off >>= 1) {
            a0 += __shfl_xor_sync(0xffffffffu, a0, off);
            a1 += __shfl_xor_sync(0xffffffffu, a1, off);
        }
        lg[0][e] = a0; lg[1][e] = a1;
    }

    if (lane == 0) {
#pragma unroll
        for (int q = 0; q < 2; q++) {
            const int t = t0 + q;
            float mx = lg[q][0];
#pragma unroll
            for (int e = 1; e < EZ_EXP; e++) mx = fmaxf(mx, lg[q][e]);
            float sc[EZ_EXP], s = 0.f;
#pragma unroll
            for (int e = 0; e < EZ_EXP; e++) { sc[e] = __expf(lg[q][e] - mx); s += sc[e]; }
            const float inv = 1.f / s;
            float bsc[EZ_EXP];
#pragma unroll
            for (int e = 0; e < EZ_EXP; e++) { sc[e] *= inv; bsc[e] = sc[e] + bias[e]; }

            int i1 = 0;
#pragma unroll
            for (int e = 1; e < EZ_EXP; e++) if (bsc[e] > bsc[i1]) i1 = e;
            int i2 = (i1 == 0) ? 1 : 0;
#pragma unroll
            for (int e = 0; e < EZ_EXP; e++) if (e != i1 && bsc[e] > bsc[i2]) i2 = e;

            const float w1 = sc[i1], w2v = sc[i2];
            g_top_idx[2 * t] = i1;  g_top_idx[2 * t + 1] = i2;
            g_top_w[2 * t] = w1;    g_top_w[2 * t + 1] = w2v;
            float zs = 0.f;
            if (i1 >= E_EXP) zs += w1;
            if (i2 >= E_EXP) zs += w2v;
            g_zero_scale[t] = zs;

            if (i1 < E_EXP) atomicAdd(&g_blk[i1][chunk], 1);
            if (i2 < E_EXP) atomicAdd(&g_blk[i2][chunk], 1);
        }
    }
}

// ============================================================================
// single-sync stable scatter. grid (E, 16); warp w owns slots [w*128, w*128+128)
// of its chunk. Ordering identical to the serial scan.
// ============================================================================
__global__ void __launch_bounds__(256) scatter_kernel()
{
    const int e = blockIdx.x, j = blockIdx.y;
    const int tid = threadIdx.x, lane = tid & 31, w = tid >> 5;
    __shared__ int wtot[8];

    unsigned bal[4];
    int cnt = 0;
#pragma unroll
    for (int it = 0; it < 4; it++) {
        const int slot = j * 1024 + w * 128 + it * 32 + lane;
        const int f = (g_top_idx[slot] == e) ? 1 : 0;
        bal[it] = __ballot_sync(0xffffffffu, f);
        cnt += __popc(bal[it]);
    }
    if (lane == 0) wtot[w] = cnt;
    __syncthreads();

    // chunk base from router-built g_blk + warp prefix within chunk
    int cbase = 0;
#pragma unroll
    for (int i = 0; i < 16; i++) {
        const int v = g_blk[e][i];
        if (i < j) cbase += v;
    }
    if (tid == 0 && j == 0) {
        int tot = 0;
#pragma unroll
        for (int i = 0; i < 16; i++) tot += g_blk[e][i];
        g_counts[e] = tot;
    }
    int run = cbase;
    for (int i = 0; i < w; i++) run += wtot[i];

#pragma unroll
    for (int it = 0; it < 4; it++) {
        const int slot = j * 1024 + w * 128 + it * 32 + lane;
        if ((bal[it] >> lane) & 1u) {
            const int pos = run + __popc(bal[it] & ((1u << lane) - 1u));
            g_rows[e * T_TOK + pos] = slot;
        }
        run += __popc(bal[it]);
    }
}

// ============================================================================
// HMMA GEMMs — champion config (R6/R9), byte-identical mainloops.
// CTA 128x128, 8 warps (2Mx4N), warp tile 64x32, K chunk 32, NSTG=4.
// ============================================================================
#define ROWB   80
#define MATB   (128 * ROWB)        // 10240
#define STAGE  (2 * MATB)          // 20480
#define NSTG   4
#define SMEM_DYN (NSTG * STAGE)    // 81920

// ---- up GEMM + SiLU: A = x(fp16), B = w13 interleaved gate/up. grid (E*64, 8)
__global__ void __launch_bounds__(256, 2) up_gemm_mma()
{
    const int e  = blockIdx.x >> 6;
    const int mt = blockIdx.x & 63;
    const int cnt = g_counts[e];
    const int m0 = mt * 128;
    if (m0 >= cnt) return;
    const int rcount = min(128, cnt - m0);
    const int ib = blockIdx.y * 64;

    extern __shared__ char sm[];
    const u32 smu = smem_u32(sm);
    __shared__ int s_slot[128];
    __shared__ int s_tok[128];

    const int tid = threadIdx.x, lane = tid & 31, wid = tid >> 5;
    const int wm = wid >> 2, wn = wid & 3;

    if (tid < 128) {
        const int sl = g_rows[e * T_TOK + m0 + min(tid, rcount - 1)];
        s_slot[tid] = sl;
        s_tok[tid] = sl >> 1;
    }
    __syncthreads();

    const char* srcs[4];
    u32 dsts[4];
#pragma unroll
    for (int t = 0; t < 4; t++) {
        const int idx = tid + t * 256;
        const int mat = idx >> 9, rr = (idx >> 2) & 127, ch = idx & 3;
        dsts[t] = (u32)(mat * MATB + rr * ROWB + ch * 16);
        if (mat == 0) srcs[t] = (const char*)(g_xh + (size_t)s_tok[rr] * H_DIM + ch * 8);
        else {
            const int wrow = (rr & 1) ? (512 + ib + (rr >> 1)) : (ib + (rr >> 1));
            srcs[t] = (const char*)(g_w13h + ((size_t)e * 1024 + wrow) * H_DIM + ch * 8);
        }
    }

    float acc[4][4][4];
#pragma unroll
    for (int i = 0; i < 4; i++)
#pragma unroll
        for (int j = 0; j < 4; j++)
#pragma unroll
            for (int q = 0; q < 4; q++) acc[i][j][q] = 0.f;

#pragma unroll
    for (int s = 0; s < 3; s++) {
#pragma unroll
        for (int t = 0; t < 4; t++) CPA16(smu + s * STAGE + dsts[t], srcs[t] + (size_t)s * 64);
        CPCOMMIT();
    }

    const u32 lrow = (u32)(lane & 15) * ROWB + (u32)((lane >> 4) << 4);

#pragma unroll 1
    for (int c = 0; c < 32; c++) {
        const int p = c & 3;
        CPWAIT2();
        __syncthreads();
        if (c + 3 < 32) {
            const u32 sb = smu + ((c + 3) & 3) * STAGE;
            const size_t go = (size_t)(c + 3) * 64;
#pragma unroll
            for (int t = 0; t < 4; t++) CPA16(sb + dsts[t], srcs[t] + go);
        }
        CPCOMMIT();

        const u32 aB = smu + p * STAGE + (u32)(wm * 64) * ROWB + lrow;
        const u32 bB = smu + p * STAGE + MATB + (u32)(wn * 32) * ROWB + lrow;
#pragma unroll
        for (int kk = 0; kk < 2; kk++) {
            const u32 ko = kk * 32;
            u32 a[4][4], b[2][4];
#pragma unroll
            for (int mi = 0; mi < 4; mi++)
                ldsm4(a[mi][0], a[mi][1], a[mi][2], a[mi][3], aB + mi * 16 * ROWB + ko);
            ldsm4(b[0][0], b[0][1], b[0][2], b[0][3], bB + ko);
            ldsm4(b[1][0], b[1][1], b[1][2], b[1][3], bB + 16 * ROWB + ko);
#pragma unroll
            for (int mi = 0; mi < 4; mi++)
#pragma unroll
                for (int nj = 0; nj < 4; nj++) {
                    const int g = nj >> 1, o = nj & 1;
                    mma_f16(acc[mi][nj], a[mi], b[g][o], b[g][o + 2]);
                }
        }
    }

    const int qr = lane >> 2, qc = lane & 3;
#pragma unroll
    for (int mi = 0; mi < 4; mi++) {
        const int mlo = wm * 64 + mi * 16 + qr;
#pragma unroll
        for (int nj = 0; nj < 4; nj++) {
            const int icol = ib + wn * 16 + nj * 4 + qc;
            const float* a4 = acc[mi][nj];
            if (mlo < rcount) {
                const float g = a4[0], u = a4[1];
                g_acth[(size_t)s_slot[mlo] * I_DIM + icol] =
                    __float2half_rn(g / (1.f + __expf(-g)) * u);
            }
            if (mlo + 8 < rcount) {
                const float g = a4[2], u = a4[3];
                g_acth[(size_t)s_slot[mlo + 8] * I_DIM + icol] =
                    __float2half_rn(g / (1.f + __expf(-g)) * u);
            }
        }
    }
}

// ---- down GEMM: A = act(fp16), B = w2. K=512 (16 chunks). grid (E*64, 8) ----
__global__ void __launch_bounds__(256, 2) down_gemm_mma()
{
    const int e  = blockIdx.x >> 6;
    const int mt = blockIdx.x & 63;
    const int cnt = g_counts[e];
    const int m0 = mt * 128;
    if (m0 >= cnt) return;
    const int rcount = min(128, cnt - m0);
    const int hb = blockIdx.y * 128;

    extern __shared__ char sm[];
    const u32 smu = smem_u32(sm);
    __shared__ int   s_slot[128];
    __shared__ float s_wt[128];

    const int tid = threadIdx.x, lane = tid & 31, wid = tid >> 5;
    const int wm = wid >> 2, wn = wid & 3;

    if (tid < 128) {
        const int sl = g_rows[e * T_TOK + m0 + min(tid, rcount - 1)];
        s_slot[tid] = sl;
        s_wt[tid] = g_top_w[sl] * SCALE_F;
    }
    __syncthreads();

    const char* srcs[4];
    u32 dsts[4];
#pragma unroll
    for (int t = 0; t < 4; t++) {
        const int idx = tid + t * 256;
        const int mat = idx >> 9, rr = (idx >> 2) & 127, ch = idx & 3;
        dsts[t] = (u32)(mat * MATB + rr * ROWB + ch * 16);
        if (mat == 0) srcs[t] = (const char*)(g_acth + (size_t)s_slot[rr] * I_DIM + ch * 8);
        else srcs[t] = (const char*)(g_w2h + ((size_t)e * H_DIM + hb + rr) * I_DIM + ch * 8);
    }

    float acc[4][4][4];
#pragma unroll
    for (int i = 0; i < 4; i++)
#pragma unroll
        for (int j = 0; j < 4; j++)
#pragma unroll
            for (int q = 0; q < 4; q++) acc[i][j][q] = 0.f;

#pragma unroll
    for (int s = 0; s < 3; s++) {
#pragma unroll
        for (int t = 0; t < 4; t++) CPA16(smu + s * STAGE + dsts[t], srcs[t] + (size_t)s * 64);
        CPCOMMIT();
    }

    const u32 lrow = (u32)(lane & 15) * ROWB + (u32)((lane >> 4) << 4);

#pragma unroll 1
    for (int c = 0; c < 16; c++) {
        const int p = c & 3;
        CPWAIT2();
        __syncthreads();
        if (c + 3 < 16) {
            const u32 sb = smu + ((c + 3) & 3) * STAGE;
            const size_t go = (size_t)(c + 3) * 64;
#pragma unroll
            for (int t = 0; t < 4; t++) CPA16(sb + dsts[t], srcs[t] + go);
        }
        CPCOMMIT();

        const u32 aB = smu + p * STAGE + (u32)(wm * 64) * ROWB + lrow;
        const u32 bB = smu + p * STAGE + MATB + (u32)(wn * 32) * ROWB + lrow;
#pragma unroll
        for (int kk = 0; kk < 2; kk++) {
            const u32 ko = kk * 32;
            u32 a[4][4], b[2][4];
#pragma unroll
            for (int mi = 0; mi < 4; mi++)
                ldsm4(a[mi][0], a[mi][1], a[mi][2], a[mi][3], aB + mi * 16 * ROWB + ko);
            ldsm4(b[0][0], b[0][1], b[0][2], b[0][3], bB + ko);
            ldsm4(b[1][0], b[1][1], b[1][2], b[1][3], bB + 16 * ROWB + ko);
#pragma unroll
            for (int mi = 0; mi < 4; mi++)
#pragma unroll
                for (int nj = 0; nj < 4; nj++) {
                    const int g = nj >> 1, o = nj & 1;
                    mma_f16(acc[mi][nj], a[mi], b[g][o], b[g][o + 2]);
                }
        }
    }

    const int qr = lane >> 2, qc = lane & 3;
#pragma unroll
    for (int mi = 0; mi < 4; mi++) {
        const int mlo = wm * 64 + mi * 16 + qr;
#pragma unroll
        for (int nj = 0; nj < 4; nj++) {
            const int n0 = hb + wn * 32 + nj * 8 + 2 * qc;
            const float* a4 = acc[mi][nj];
            if (mlo < rcount) {
                const float wt = s_wt[mlo];
                *(__half2*)(g_yh + (size_t)s_slot[mlo] * H_DIM + n0) =
                    __halves2half2(__float2half_rn(wt * a4[0]), __float2half_rn(wt * a4[1]));
            }
            if (mlo + 8 < rcount) {
                const float wt = s_wt[mlo + 8];
                *(__half2*)(g_yh + (size_t)s_slot[mlo + 8] * H_DIM + n0) =
                    __halves2half2(__float2half_rn(wt * a4[2]), __float2half_rn(wt * a4[3]));
            }
        }
    }
}

// ============================================================================
// finalize: out = zero_scale*x + slot sums (fp16 y)
// ============================================================================
__global__ void __launch_bounds__(256) finalize_kernel(
    const float* __restrict__ x, float* __restrict__ out)
{
    const int t = blockIdx.x;
    const float zs = g_zero_scale[t];
    const bool r0 = g_top_idx[2 * t]     < E_EXP;
    const bool r1 = g_top_idx[2 * t + 1] < E_EXP;
    const int h = threadIdx.x * 4;

    float4 xv = *(const float4*)(x + (size_t)t * H_DIM + h);
    float4 o;
    o.x = zs * xv.x; o.y = zs * xv.y; o.z = zs * xv.z; o.w = zs * xv.w;
    if (r0) {
        const __half2* y = (const __half2*)(g_yh + (size_t)(2 * t) * H_DIM + h);
        const float2 a = __half22float2(y[0]), b = __half22float2(y[1]);
        o.x += a.x; o.y += a.y; o.z += b.x; o.w += b.y;
    }
    if (r1) {
        const __half2* y = (const __half2*)(g_yh + (size_t)(2 * t + 1) * H_DIM + h);
        const float2 a = __half22float2(y[0]), b = __half22float2(y[1]);
        o.x += a.x; o.y += a.y; o.z += b.x; o.w += b.y;
    }
    *(float4*)(out + (size_t)t * H_DIM + h) = o;
}

// ============================================================================
// launch
// ============================================================================
extern "C" void kernel_launch(void* const* d_in, const int* in_sizes, int n_in,
                              void* d_out, int out_size)
{
    const float* x    = (const float*)d_in[0];
    const float* rw   = (const float*)d_in[1];
    const float* bias = (const float*)d_in[2];
    const float* w13  = (const float*)d_in[3];
    const float* w2   = (const float*)d_in[4];
    float* out = (float*)d_out;

    cudaFuncSetAttribute(up_gemm_mma,   cudaFuncAttributeMaxDynamicSharedMemorySize, SMEM_DYN);
    cudaFuncSetAttribute(down_gemm_mma, cudaFuncAttributeMaxDynamicSharedMemorySize, SMEM_DYN);

    cvt_w_kernel<<<(int)((W13_ELEMS + (size_t)E_EXP * H_DIM * I_DIM) / 1024), 256>>>(w13, w2);
    router_kernel<<<T_TOK / 16, 256>>>(x, rw, bias);

    dim3 gl(E_EXP, 16);
    scatter_kernel<<<gl, 256>>>();

    dim3 gu(E_EXP * 64, 8);
    up_gemm_mma<<<gu, 256, SMEM_DYN>>>();

    dim3 gd(E_EXP * 64, 8);
    down_gemm_mma<<<gd, 256, SMEM_DYN>>>();

    finalize_kernel<<<T_TOK, 256>>>(x, out);
}

// round 12
// speedup vs baseline: 1.2576x; 1.0602x over previous
#include <cuda_runtime.h>
#include <cuda_fp16.h>
#include <cstdint>

#define T_TOK   8192
#define H_DIM   1024
#define I_DIM   512
#define E_EXP   8
#define EZ_EXP  12
#define SCALE_F 2.5f

typedef unsigned int u32;
typedef unsigned long long u64;

// ---------------- scratch (device globals; no allocation) ----------------
__device__ int    g_top_idx[T_TOK * 2];
__device__ float  g_top_w[T_TOK * 2];
__device__ float  g_zero_scale[T_TOK];
__device__ int    g_counts[E_EXP];
__device__ int    g_blk[E_EXP][16];
__device__ int    g_rows[E_EXP * T_TOK];
__device__ __half g_xh[(size_t)T_TOK * H_DIM];
__device__ __half g_w13h[(size_t)E_EXP * 2 * I_DIM * H_DIM];
__device__ __half g_w2h[(size_t)E_EXP * H_DIM * I_DIM];
__device__ __half g_acth[(size_t)T_TOK * 2 * I_DIM];
__device__ __half g_yh[(size_t)T_TOK * 2 * H_DIM];

// ---------------- helpers ----------------
__device__ __forceinline__ u32 smem_u32(const void* p) {
    u32 a;
    asm("{ .reg .u64 t; cvta.to.shared.u64 t, %1; cvt.u32.u64 %0, t; }" : "=r"(a) : "l"(p));
    return a;
}

#define CPA16(dst, src) \
    asm volatile("{.reg .u64 g; cvta.to.global.u64 g, %1; cp.async.cg.shared.global [%0], [g], 16;}\n" \
                 :: "r"((u32)(dst)), "l"(src) : "memory")
#define CPCOMMIT() asm volatile("cp.async.commit_group;" ::: "memory")
#define CPWAIT0()  asm volatile("cp.async.wait_group 0;" ::: "memory")

__device__ __forceinline__ void ldsm4(u32& r0, u32& r1, u32& r2, u32& r3, u32 addr) {
    asm volatile("ldmatrix.sync.aligned.m8n8.x4.shared.b16 {%0,%1,%2,%3}, [%4];"
                 : "=r"(r0), "=r"(r1), "=r"(r2), "=r"(r3) : "r"(addr));
}

__device__ __forceinline__ void mma_f16(float* d, const u32* a, u32 b0, u32 b1) {
    asm volatile("mma.sync.aligned.m16n8k16.row.col.f32.f16.f16.f32 "
        "{%0,%1,%2,%3}, {%4,%5,%6,%7}, {%8,%9}, {%0,%1,%2,%3};"
        : "+f"(d[0]), "+f"(d[1]), "+f"(d[2]), "+f"(d[3])
        : "r"(a[0]), "r"(a[1]), "r"(a[2]), "r"(a[3]), "r"(b0), "r"(b1));
}

// ============================================================================
// weight conversion (one-time) + zero g_blk for the router's atomic counting
// ============================================================================
#define W13_ELEMS ((size_t)E_EXP * 2 * I_DIM * H_DIM)
__global__ void __launch_bounds__(256) cvt_w_kernel(
    const float* __restrict__ w13, const float* __restrict__ w2)
{
    if (blockIdx.x == 0 && threadIdx.x < E_EXP * 16)
        ((int*)g_blk)[threadIdx.x] = 0;

    const size_t gid = (size_t)blockIdx.x * 256 + threadIdx.x;
    const float* src; __half* dst; size_t off;
    if (gid < W13_ELEMS / 4) { src = w13; dst = g_w13h; off = gid * 4; }
    else { src = w2; dst = g_w2h; off = (gid - W13_ELEMS / 4) * 4; }
    const float4 v = *(const float4*)(src + off);
    *(__half2*)(dst + off)     = __halves2half2(__float2half_rn(v.x), __float2half_rn(v.y));
    *(__half2*)(dst + off + 2) = __halves2half2(__float2half_rn(v.z), __float2half_rn(v.w));
}

// ============================================================================
// router + fused x->fp16 conversion + fused per-chunk expert counting (proven)
// ============================================================================
__global__ void __launch_bounds__(256) router_kernel(
    const float* __restrict__ x, const float* __restrict__ rw, const float* __restrict__ bias)
{
    __shared__ float srw[EZ_EXP * H_DIM];
    const int tid = threadIdx.x;
    for (int i = tid; i < EZ_EXP * H_DIM; i += 256) srw[i] = rw[i];
    __syncthreads();

    const int warp = tid >> 5, lane = tid & 31;
    const int t0 = blockIdx.x * 16 + warp * 2;
    const int chunk = blockIdx.x >> 5;
    const float* xr0 = x + (size_t)t0 * H_DIM;
    const float* xr1 = x + (size_t)(t0 + 1) * H_DIM;

    float xv0[32], xv1[32];
#pragma unroll
    for (int j = 0; j < 32; j++) { xv0[j] = xr0[lane + 32 * j]; xv1[j] = xr1[lane + 32 * j]; }

    __half* xh0 = g_xh + (size_t)t0 * H_DIM;
    __half* xh1 = g_xh + (size_t)(t0 + 1) * H_DIM;
#pragma unroll
    for (int j = 0; j < 32; j++) {
        xh0[lane + 32 * j] = __float2half_rn(xv0[j]);
        xh1[lane + 32 * j] = __float2half_rn(xv1[j]);
    }

    float lg[2][EZ_EXP];
#pragma unroll
    for (int e = 0; e < EZ_EXP; e++) {
        const float* wr = srw + e * H_DIM;
        float a0 = 0.f, a1 = 0.f;
#pragma unroll
        for (int j = 0; j < 32; j++) {
            const float w = wr[lane + 32 * j];
            a0 += xv0[j] * w;
            a1 += xv1[j] * w;
        }
#pragma unroll
        for (int off = 16; off; off >>= 1) {
            a0 += __shfl_xor_sync(0xffffffffu, a0, off);
            a1 += __shfl_xor_sync(0xffffffffu, a1, off);
        }
        lg[0][e] = a0; lg[1][e] = a1;
    }

    if (lane == 0) {
#pragma unroll
        for (int q = 0; q < 2; q++) {
            const int t = t0 + q;
            float mx = lg[q][0];
#pragma unroll
            for (int e = 1; e < EZ_EXP; e++) mx = fmaxf(mx, lg[q][e]);
            float sc[EZ_EXP], s = 0.f;
#pragma unroll
            for (int e = 0; e < EZ_EXP; e++) { sc[e] = __expf(lg[q][e] - mx); s += sc[e]; }
            const float inv = 1.f / s;
            float bsc[EZ_EXP];
#pragma unroll
            for (int e = 0; e < EZ_EXP; e++) { sc[e] *= inv; bsc[e] = sc[e] + bias[e]; }

            int i1 = 0;
#pragma unroll
            for (int e = 1; e < EZ_EXP; e++) if (bsc[e] > bsc[i1]) i1 = e;
            int i2 = (i1 == 0) ? 1 : 0;
#pragma unroll
            for (int e = 0; e < EZ_EXP; e++) if (e != i1 && bsc[e] > bsc[i2]) i2 = e;

            const float w1 = sc[i1], w2v = sc[i2];
            g_top_idx[2 * t] = i1;  g_top_idx[2 * t + 1] = i2;
            g_top_w[2 * t] = w1;    g_top_w[2 * t + 1] = w2v;
            float zs = 0.f;
            if (i1 >= E_EXP) zs += w1;
            if (i2 >= E_EXP) zs += w2v;
            g_zero_scale[t] = zs;

            if (i1 < E_EXP) atomicAdd(&g_blk[i1][chunk], 1);
            if (i2 < E_EXP) atomicAdd(&g_blk[i2][chunk], 1);
        }
    }
}

// ============================================================================
// single-sync stable scatter (proven)
// ============================================================================
__global__ void __launch_bounds__(256) scatter_kernel()
{
    const int e = blockIdx.x, j = blockIdx.y;
    const int tid = threadIdx.x, lane = tid & 31, w = tid >> 5;
    __shared__ int wtot[8];

    unsigned bal[4];
    int cnt = 0;
#pragma unroll
    for (int it = 0; it < 4; it++) {
        const int slot = j * 1024 + w * 128 + it * 32 + lane;
        const int f = (g_top_idx[slot] == e) ? 1 : 0;
        bal[it] = __ballot_sync(0xffffffffu, f);
        cnt += __popc(bal[it]);
    }
    if (lane == 0) wtot[w] = cnt;
    __syncthreads();

    int cbase = 0;
#pragma unroll
    for (int i = 0; i < 16; i++) {
        const int v = g_blk[e][i];
        if (i < j) cbase += v;
    }
    if (tid == 0 && j == 0) {
        int tot = 0;
#pragma unroll
        for (int i = 0; i < 16; i++) tot += g_blk[e][i];
        g_counts[e] = tot;
    }
    int run = cbase;
    for (int i = 0; i < w; i++) run += wtot[i];

#pragma unroll
    for (int it = 0; it < 4; it++) {
        const int slot = j * 1024 + w * 128 + it * 32 + lane;
        if ((bal[it] >> lane) & 1u) {
            const int pos = run + __popc(bal[it] & ((1u << lane) - 1u));
            g_rows[e * T_TOK + pos] = slot;
        }
        run += __popc(bal[it]);
    }
}

// ============================================================================
// HMMA GEMMs. CTA 128x128, 8 warps (2Mx4N), warp tile 64x32.
// K chunk 64 (4 kk), NSTG=2. Rows padded to 144B (conflict-free: 144 mod 128 = 16).
// Per-iter (race-free): WAIT0 -> sync -> issue c+1 into p^1 -> commit -> compute p.
// ============================================================================
#define ROWB   144
#define MATB   (128 * ROWB)          // 18432
#define STAGE  (2 * MATB)            // 36864
#define SMEM_DYN (2 * STAGE)         // 73728

// ---- up GEMM + SiLU: A = x(fp16), B = w13 interleaved gate/up. grid (E*64, 8)
__global__ void __launch_bounds__(256, 2) up_gemm_mma()
{
    const int e  = blockIdx.x >> 6;
    const int mt = blockIdx.x & 63;
    const int cnt = g_counts[e];
    const int m0 = mt * 128;
    if (m0 >= cnt) return;
    const int rcount = min(128, cnt - m0);
    const int ib = blockIdx.y * 64;

    extern __shared__ char sm[];
    const u32 smu = smem_u32(sm);
    __shared__ int s_slot[128];
    __shared__ int s_tok[128];

    const int tid = threadIdx.x, lane = tid & 31, wid = tid >> 5;
    const int wm = wid >> 2, wn = wid & 3;

    if (tid < 128) {
        const int sl = g_rows[e * T_TOK + m0 + min(tid, rcount - 1)];
        s_slot[tid] = sl;
        s_tok[tid] = sl >> 1;
    }
    __syncthreads();

    // loads: per stage 2048 16B chunks (A 1024 + B 1024); 8 per thread.
    const int rr0 = tid >> 3, ch = tid & 7;
    const u32 dstA = (u32)(rr0 * ROWB + ch * 16);
    const u32 dstB = (u32)(MATB + rr0 * ROWB + ch * 16);
    const char* srcA[4];
    const char* srcB[4];
#pragma unroll
    for (int t = 0; t < 4; t++) {
        const int rr = rr0 + 32 * t;
        srcA[t] = (const char*)(g_xh + (size_t)s_tok[rr] * H_DIM + ch * 8);
        const int wrow = (rr & 1) ? (512 + ib + (rr >> 1)) : (ib + (rr >> 1));
        srcB[t] = (const char*)(g_w13h + ((size_t)e * 1024 + wrow) * H_DIM + ch * 8);
    }

    float acc[4][4][4];
#pragma unroll
    for (int i = 0; i < 4; i++)
#pragma unroll
        for (int j = 0; j < 4; j++)
#pragma unroll
            for (int q = 0; q < 4; q++) acc[i][j][q] = 0.f;

    // prologue: stage 0 <- chunk 0
#pragma unroll
    for (int t = 0; t < 4; t++) {
        CPA16(smu + dstA + t * 32 * ROWB, srcA[t]);
        CPA16(smu + dstB + t * 32 * ROWB, srcB[t]);
    }
    CPCOMMIT();

    const u32 lrow = (u32)(lane & 15) * ROWB + (u32)((lane >> 4) << 4);

#pragma unroll 1
    for (int c = 0; c < 16; c++) {
        const int p = c & 1;
        CPWAIT0();                 // chunk c complete (this thread)
        __syncthreads();           // stage p visible to all; all done computing c-1 ⇒ p^1 free
        if (c + 1 < 16) {
            const u32 sb = smu + (p ^ 1) * STAGE;
            const size_t go = (size_t)(c + 1) * 128;
#pragma unroll
            for (int t = 0; t < 4; t++) {
                CPA16(sb + dstA + t * 32 * ROWB, srcA[t] + go);
                CPA16(sb + dstB + t * 32 * ROWB, srcB[t] + go);
            }
        }
        CPCOMMIT();

        const u32 aB = smu + p * STAGE + (u32)(wm * 64) * ROWB + lrow;
        const u32 bB = smu + p * STAGE + MATB + (u32)(wn * 32) * ROWB + lrow;
#pragma unroll
        for (int kk = 0; kk < 4; kk++) {
            const u32 ko = kk * 32;
            u32 a[4][4], b[2][4];
#pragma unroll
            for (int mi = 0; mi < 4; mi++)
                ldsm4(a[mi][0], a[mi][1], a[mi][2], a[mi][3], aB + mi * 16 * ROWB + ko);
            ldsm4(b[0][0], b[0][1], b[0][2], b[0][3], bB + ko);
            ldsm4(b[1][0], b[1][1], b[1][2], b[1][3], bB + 16 * ROWB + ko);
#pragma unroll
            for (int mi = 0; mi < 4; mi++)
#pragma unroll
                for (int nj = 0; nj < 4; nj++) {
                    const int g = nj >> 1, o = nj & 1;
                    mma_f16(acc[mi][nj], a[mi], b[g][o], b[g][o + 2]);
                }
        }
    }

    const int qr = lane >> 2, qc = lane & 3;
#pragma unroll
    for (int mi = 0; mi < 4; mi++) {
        const int mlo = wm * 64 + mi * 16 + qr;
#pragma unroll
        for (int nj = 0; nj < 4; nj++) {
            const int icol = ib + wn * 16 + nj * 4 + qc;
            const float* a4 = acc[mi][nj];
            if (mlo < rcount) {
                const float g = a4[0], u = a4[1];
                g_acth[(size_t)s_slot[mlo] * I_DIM + icol] =
                    __float2half_rn(g / (1.f + __expf(-g)) * u);
            }
            if (mlo + 8 < rcount) {
                const float g = a4[2], u = a4[3];
                g_acth[(size_t)s_slot[mlo + 8] * I_DIM + icol] =
                    __float2half_rn(g / (1.f + __expf(-g)) * u);
            }
        }
    }
}

// ---- down GEMM: A = act(fp16), B = w2. K=512 (8 chunks of 64). grid (E*64, 8)
__global__ void __launch_bounds__(256, 2) down_gemm_mma()
{
    const int e  = blockIdx.x >> 6;
    const int mt = blockIdx.x & 63;
    const int cnt = g_counts[e];
    const int m0 = mt * 128;
    if (m0 >= cnt) return;
    const int rcount = min(128, cnt - m0);
    const int hb = blockIdx.y * 128;

    extern __shared__ char sm[];
    const u32 smu = smem_u32(sm);
    __shared__ int   s_slot[128];
    __shared__ float s_wt[128];

    const int tid = threadIdx.x, lane = tid & 31, wid = tid >> 5;
    const int wm = wid >> 2, wn = wid & 3;

    if (tid < 128) {
        const int sl = g_rows[e * T_TOK + m0 + min(tid, rcount - 1)];
        s_slot[tid] = sl;
        s_wt[tid] = g_top_w[sl] * SCALE_F;
    }
    __syncthreads();

    const int rr0 = tid >> 3, ch = tid & 7;
    const u32 dstA = (u32)(rr0 * ROWB + ch * 16);
    const u32 dstB = (u32)(MATB + rr0 * ROWB + ch * 16);
    const char* srcA[4];
    const char* srcB[4];
#pragma unroll
    for (int t = 0; t < 4; t++) {
        const int rr = rr0 + 32 * t;
        srcA[t] = (const char*)(g_acth + (size_t)s_slot[rr] * I_DIM + ch * 8);
        srcB[t] = (const char*)(g_w2h + ((size_t)e * H_DIM + hb + rr) * I_DIM + ch * 8);
    }

    float acc[4][4][4];
#pragma unroll
    for (int i = 0; i < 4; i++)
#pragma unroll
        for (int j = 0; j < 4; j++)
#pragma unroll
            for (int q = 0; q < 4; q++) acc[i][j][q] = 0.f;

#pragma unroll
    for (int t = 0; t < 4; t++) {
        CPA16(smu + dstA + t * 32 * ROWB, srcA[t]);
        CPA16(smu + dstB + t * 32 * ROWB, srcB[t]);
    }
    CPCOMMIT();

    const u32 lrow = (u32)(lane & 15) * ROWB + (u32)((lane >> 4) << 4);

#pragma unroll 1
    for (int c = 0; c < 8; c++) {
        const int p = c & 1;
        CPWAIT0();
        __syncthreads();
        if (c + 1 < 8) {
            const u32 sb = smu + (p ^ 1) * STAGE;
            const size_t go = (size_t)(c + 1) * 128;
#pragma unroll
            for (int t = 0; t < 4; t++) {
                CPA16(sb + dstA + t * 32 * ROWB, srcA[t] + go);
                CPA16(sb + dstB + t * 32 * ROWB, srcB[t] + go);
            }
        }
        CPCOMMIT();

        const u32 aB = smu + p * STAGE + (u32)(wm * 64) * ROWB + lrow;
        const u32 bB = smu + p * STAGE + MATB + (u32)(wn * 32) * ROWB + lrow;
#pragma unroll
        for (int kk = 0; kk < 4; kk++) {
            const u32 ko = kk * 32;
            u32 a[4][4], b[2][4];
#pragma unroll
            for (int mi = 0; mi < 4; mi++)
                ldsm4(a[mi][0], a[mi][1], a[mi][2], a[mi][3], aB + mi * 16 * ROWB + ko);
            ldsm4(b[0][0], b[0][1], b[0][2], b[0][3], bB + ko);
            ldsm4(b[1][0], b[1][1], b[1][2], b[1][3], bB + 16 * ROWB + ko);
#pragma unroll
            for (int mi = 0; mi < 4; mi++)
#pragma unroll
                for (int nj = 0; nj < 4; nj++) {
                    const int g = nj >> 1, o = nj & 1;
                    mma_f16(acc[mi][nj], a[mi], b[g][o], b[g][o + 2]);
                }
        }
    }

    const int qr = lane >> 2, qc = lane & 3;
#pragma unroll
    for (int mi = 0; mi < 4; mi++) {
        const int mlo = wm * 64 + mi * 16 + qr;
#pragma unroll
        for (int nj = 0; nj < 4; nj++) {
            const int n0 = hb + wn * 32 + nj * 8 + 2 * qc;
            const float* a4 = acc[mi][nj];
            if (mlo < rcount) {
                const float wt = s_wt[mlo];
                *(__half2*)(g_yh + (size_t)s_slot[mlo] * H_DIM + n0) =
                    __halves2half2(__float2half_rn(wt * a4[0]), __float2half_rn(wt * a4[1]));
            }
            if (mlo + 8 < rcount) {
                const float wt = s_wt[mlo + 8];
                *(__half2*)(g_yh + (size_t)s_slot[mlo + 8] * H_DIM + n0) =
                    __halves2half2(__float2half_rn(wt * a4[2]), __float2half_rn(wt * a4[3]));
            }
        }
    }
}

// ============================================================================
// finalize: out = zero_scale*x + slot sums (fp16 y)
// ============================================================================
__global__ void __launch_bounds__(256) finalize_kernel(
    const float* __restrict__ x, float* __restrict__ out)
{
    const int t = blockIdx.x;
    const float zs = g_zero_scale[t];
    const bool r0 = g_top_idx[2 * t]     < E_EXP;
    const bool r1 = g_top_idx[2 * t + 1] < E_EXP;
    const int h = threadIdx.x * 4;

    float4 xv = *(const float4*)(x + (size_t)t * H_DIM + h);
    float4 o;
    o.x = zs * xv.x; o.y = zs * xv.y; o.z = zs * xv.z; o.w = zs * xv.w;
    if (r0) {
        const __half2* y = (const __half2*)(g_yh + (size_t)(2 * t) * H_DIM + h);
        const float2 a = __half22float2(y[0]), b = __half22float2(y[1]);
        o.x += a.x; o.y += a.y; o.z += b.x; o.w += b.y;
    }
    if (r1) {
        const __half2* y = (const __half2*)(g_yh + (size_t)(2 * t + 1) * H_DIM + h);
        const float2 a = __half22float2(y[0]), b = __half22float2(y[1]);
        o.x += a.x; o.y += a.y; o.z += b.x; o.w += b.y;
    }
    *(float4*)(out + (size_t)t * H_DIM + h) = o;
}

// ============================================================================
// launch
// ============================================================================
extern "C" void kernel_launch(void* const* d_in, const int* in_sizes, int n_in,
                              void* d_out, int out_size)
{
    const float* x    = (const float*)d_in[0];
    const float* rw   = (const float*)d_in[1];
    const float* bias = (const float*)d_in[2];
    const float* w13  = (const float*)d_in[3];
    const float* w2   = (const float*)d_in[4];
    float* out = (float*)d_out;

    cudaFuncSetAttribute(up_gemm_mma,   cudaFuncAttributeMaxDynamicSharedMemorySize, SMEM_DYN);
    cudaFuncSetAttribute(down_gemm_mma, cudaFuncAttributeMaxDynamicSharedMemorySize, SMEM_DYN);

    cvt_w_kernel<<<(int)((W13_ELEMS + (size_t)E_EXP * H_DIM * I_DIM) / 1024), 256>>>(w13, w2);
    router_kernel<<<T_TOK / 16, 256>>>(x, rw, bias);

    dim3 gl(E_EXP, 16);
    scatter_kernel<<<gl, 256>>>();

    dim3 gu(E_EXP * 64, 8);
    up_gemm_mma<<<gu, 256, SMEM_DYN>>>();

    dim3 gd(E_EXP * 64, 8);
    down_gemm_mma<<<gd, 256, SMEM_DYN>>>();

    finalize_kernel<<<T_TOK, 256>>>(x, out);
}